// round 11
// baseline (speedup 1.0000x reference)
#include <cuda_runtime.h>
#include <cuda_fp16.h>
#include <stdint.h>
#include <math.h>

#define N_FRAMES 2048
#define N_AGENTS 32
#define N_ROWS 65536
#define FEAT 512
#define HID 140
#define OUT2 256

#define OFF_A0 (N_ROWS * OUT2)
#define OFF_A1 (OFF_A0 + N_ROWS * 8)
#define OFF_A2 (OFF_A1 + N_ROWS * 6)

// padded dims
#define K1P 576   // 512 feat + 18 onehot + bias@530 + pad
#define N1P 144   // 140 hid + ones@140 + pad
#define K2P 144
#define KIP 1024  // cur|next
#define NIP 24

// single-fp16 transposed weights
__device__ __align__(16) __half g_w1t[N1P * K1P];     // [n][k]
__device__ __align__(16) __half g_wit[NIP * KIP];     // [n][k]
__device__ __align__(16) __half g_w2t[OUT2 * K2P];    // [n][k]

// ---------------------------------------------------------------- helpers
__device__ __forceinline__ uint32_t smaddr(const void* p) {
    return (uint32_t)__cvta_generic_to_shared(p);
}
__device__ __forceinline__ void ldsm_x4(uint32_t* r, uint32_t a) {
    asm volatile("ldmatrix.sync.aligned.m8n8.x4.shared.b16 {%0,%1,%2,%3}, [%4];"
        : "=r"(r[0]), "=r"(r[1]), "=r"(r[2]), "=r"(r[3]) : "r"(a));
}
__device__ __forceinline__ void ldsm_x2(uint32_t* r, uint32_t a) {
    asm volatile("ldmatrix.sync.aligned.m8n8.x2.shared.b16 {%0,%1}, [%2];"
        : "=r"(r[0]), "=r"(r[1]) : "r"(a));
}
__device__ __forceinline__ void mma_f16(float* d, const uint32_t* a, const uint32_t* b) {
    asm volatile("mma.sync.aligned.m16n8k16.row.col.f32.f16.f16.f32 "
        "{%0,%1,%2,%3}, {%4,%5,%6,%7}, {%8,%9}, {%0,%1,%2,%3};"
        : "+f"(d[0]), "+f"(d[1]), "+f"(d[2]), "+f"(d[3])
        : "r"(a[0]), "r"(a[1]), "r"(a[2]), "r"(a[3]), "r"(b[0]), "r"(b[1]));
}
__device__ __forceinline__ uint32_t pack2h(__half a, __half b) {
    __half2 t; t.x = a; t.y = b;
    return *reinterpret_cast<uint32_t*>(&t);
}
__device__ __forceinline__ uint32_t pack2f(float a, float b) {
    return pack2h(__float2half_rn(a), __float2half_rn(b));
}

// ---------------------------------------------------------------- prep
__global__ void prep_kernel(
    const float* __restrict__ W1, const float* __restrict__ b1,
    const float* __restrict__ W2, const float* __restrict__ b2,
    const float* __restrict__ Wi0, const float* __restrict__ Wi1,
    const float* __restrict__ Wi2)
{
    int idx = blockIdx.x * 256 + threadIdx.x;
    if (idx < N1P * K1P) {
        int n = idx / K1P, k = idx - n * K1P;
        float v = 0.f;
        if (n < HID) {
            if (k < 530)       v = W1[(size_t)k * HID + n];
            else if (k == 530) v = b1[n];
        }
        g_w1t[idx] = __float2half_rn(v);
    }
    if (idx < OUT2 * K2P) {
        int n = idx / K2P, k = idx - n * K2P;
        float v = 0.f;
        if (k < HID)       v = W2[(size_t)k * OUT2 + n];
        else if (k == HID) v = b2[n];
        g_w2t[idx] = __float2half_rn(v);
    }
    if (idx < NIP * KIP) {
        int n = idx / KIP, k = idx - n * KIP;
        float v = 0.f;
        if (n < 8)        v = Wi0[(size_t)k * 8 + n];
        else if (n < 14)  v = Wi1[(size_t)k * 6 + (n - 8)];
        else if (n < 18)  v = Wi2[(size_t)k * 4 + (n - 14)];
        g_wit[idx] = __float2half_rn(v);
    }
}

// stage 128x64 fp32 feature chunk -> fp16 smem (stride 72 halfs)
__device__ __forceinline__ void stage_feat(
    __half* sA, const float* __restrict__ src, int row0, int c0, int tid)
{
    #pragma unroll
    for (int j = 0; j < 8; j++) {
        int i = tid + j * 256;
        int r = i >> 4, ce = (i & 15) << 2;
        float4 v = *(const float4*)(src + (size_t)(row0 + r) * FEAT + c0 + ce);
        uint2 u;
        u.x = pack2f(v.x, v.y);
        u.y = pack2f(v.z, v.w);
        *(uint2*)(sA + r * 72 + ce) = u;
    }
}
__device__ __forceinline__ void stage_b1(__half* sB, int k64, int tid)
{
    #pragma unroll
    for (int j = 0; j < 5; j++) {
        int i = tid + j * 256;                 // 144*8 = 1152 uint4
        if (i < 1152) {
            int n = i >> 3, ce = (i & 7) << 3;
            *(uint4*)(sB + n * 72 + ce) =
                *(const uint4*)(g_w1t + (size_t)n * K1P + k64 + ce);
        }
    }
}
__device__ __forceinline__ void stage_wi(__half* sW, int k64, int tid)
{
    if (tid < 192) {                           // 24*8 uint4
        int n = tid >> 3, ce = (tid & 7) << 3;
        *(uint4*)(sW + n * 72 + ce) =
            *(const uint4*)(g_wit + (size_t)n * KIP + k64 + ce);
    }
}
// special chunk (one-hot + bias-one): thread r owns row r -> race-free
__device__ __forceinline__ void stage_special(
    __half* sA, const int* __restrict__ actions, int row0, int tid)
{
    if (tid < 128) {
        int r = tid;
        #pragma unroll
        for (int q = 0; q < 8; q++)
            *(uint4*)(sA + r * 72 + q * 8) = make_uint4(0, 0, 0, 0);
        int f = (row0 + r) >> 5, ag = (row0 + r) & 31;
        int i0 = actions[(f * 3 + 0) * N_AGENTS + ag];
        int i1 = actions[(f * 3 + 1) * N_AGENTS + ag];
        int i2 = actions[(f * 3 + 2) * N_AGENTS + ag];
        __half one = __float2half_rn(1.f);
        sA[r * 72 + i0] = one;
        sA[r * 72 + 8 + i1] = one;
        sA[r * 72 + 14 + i2] = one;
        sA[r * 72 + 18] = one;                 // b1 column (k=530)
    }
}
// stage W2 chunk: 64 n-rows x 144 k (stride 152)
__device__ __forceinline__ void stage_w2(__half* sW2, int c, int tid)
{
    #pragma unroll
    for (int j = 0; j < 5; j++) {
        int i = tid + j * 256;
        if (i < 1152) {
            int n = i / 18, t = i - n * 18;
            *(uint4*)(sW2 + n * 152 + t * 8) =
                *(const uint4*)(g_w2t + (size_t)(c * 64 + n) * K2P + t * 8);
        }
    }
}

// ---------------------------------------------------------------- FUSED ALL v5
// R6 structure (128-row CTA, 2 CTAs/SM, single-buffered) with:
//  - ldsm_x4 pairing for all B operands (fewer MIO ops)
//  - inv reuses gemm1 A fragments on shared cur chunks
//  - phase3: 64x32 warp tiles, 2 chunks in flight (B bytes halved)
// smem: sA @0 18432 | sB1 @18432 20736 | sWi @39168 3456 | sL @42624 12800
//       | sHid @55424 38912; phase3 aliases W2A @0, W2B @19968. total 94336
#define SA0  0
#define SB1O 18432
#define SWIO 39168
#define SL   42624
#define SHID 55424
#define SW2A 0
#define SW2B 19968
#define SM_TOTAL 94336

__global__ __launch_bounds__(256, 2) void fused_all(
    const float* __restrict__ cur, const float* __restrict__ nxt,
    const int* __restrict__ actions, float* __restrict__ out)
{
    extern __shared__ char smem[];
    __half* sA  = (__half*)(smem + SA0);
    __half* sB1 = (__half*)(smem + SB1O);
    __half* sWi = (__half*)(smem + SWIO);
    float*  sL  = (float*) (smem + SL);
    __half* sHid = (__half*)(smem + SHID);

    const int tid = threadIdx.x, lane = tid & 31, w = tid >> 5;
    const int row0 = blockIdx.x * 128;
    const int m0 = (w >> 1) * 32;              // gemm1 warp rows
    const int wodd = w & 1;                    // n-half selector
    const int n0 = wodd * 72;
    const int mI = w * 16;                     // inv rows (== m0 + wodd*16)

    // lane-derived ldsm address pieces
    const int l15 = lane & 15;
    const int aRow = lane & 15, aKo = (lane >> 4) << 3;          // A x4
    const int bRowP = ((lane >> 4) << 3) + (lane & 7);           // B x4 pair row
    const int bKoP = ((lane >> 3) & 1) << 3;                     // B x4 k-half
    const int bRow2 = l15 & 7, bKo2 = (l15 >> 3) << 3;           // B x2

    // ================= phase 1 =================
    float acc1[2][9][4];
    #pragma unroll
    for (int a = 0; a < 2; a++)
        #pragma unroll
        for (int b = 0; b < 9; b++)
            #pragma unroll
            for (int c = 0; c < 4; c++) acc1[a][b][c] = 0.f;
    float accI[3][4];
    #pragma unroll
    for (int b = 0; b < 3; b++)
        #pragma unroll
        for (int c = 0; c < 4; c++) accI[b][c] = 0.f;

    for (int kb = 0; kb < 17; kb++) {
        if (kb) __syncthreads();
        const bool g1 = (kb < 8) || (kb == 16);
        const bool iv = (kb < 16);

        // ---- stage
        if (kb < 8)        stage_feat(sA, cur, row0, kb * 64, tid);
        else if (kb < 16)  stage_feat(sA, nxt, row0, (kb - 8) * 64, tid);
        else               stage_special(sA, actions, row0, tid);
        if (kb < 8)        stage_b1(sB1, kb * 64, tid);
        else if (kb == 16) stage_b1(sB1, 512, tid);
        if (iv)            stage_wi(sWi, kb * 64, tid);
        __syncthreads();

        // ---- compute
        const int kmax = (kb == 16) ? 2 : 4;
        for (int ks = 0; ks < kmax; ks++) {
            int k0 = ks * 16;
            uint32_t a[2][4];
            if (g1) {
                #pragma unroll
                for (int mt = 0; mt < 2; mt++)
                    ldsm_x4(a[mt], smaddr(sA + (m0 + mt * 16 + aRow) * 72 + k0 + aKo));
                // B1: 4 paired x4 + 1 tail x2
                #pragma unroll
                for (int ntp = 0; ntp < 4; ntp++) {
                    uint32_t b4[4];
                    ldsm_x4(b4, smaddr(sB1 + (n0 + ntp * 16 + bRowP) * 72 + k0 + bKoP));
                    mma_f16(acc1[0][2 * ntp],     a[0], b4);
                    mma_f16(acc1[1][2 * ntp],     a[1], b4);
                    mma_f16(acc1[0][2 * ntp + 1], a[0], b4 + 2);
                    mma_f16(acc1[1][2 * ntp + 1], a[1], b4 + 2);
                }
                {
                    uint32_t b2[2];
                    ldsm_x2(b2, smaddr(sB1 + (n0 + 64 + bRow2) * 72 + k0 + bKo2));
                    mma_f16(acc1[0][8], a[0], b2);
                    mma_f16(acc1[1][8], a[1], b2);
                }
            } else {
                // nxt chunk: only load the inv rows' fragment
                ldsm_x4(a[wodd], smaddr(sA + (mI + aRow) * 72 + k0 + aKo));
            }
            if (iv) {
                const uint32_t* ai = a[wodd];
                uint32_t b4[4], b2[2];
                ldsm_x4(b4, smaddr(sWi + (bRowP) * 72 + k0 + bKoP));         // nt 0,1
                mma_f16(accI[0], ai, b4);
                mma_f16(accI[1], ai, b4 + 2);
                ldsm_x2(b2, smaddr(sWi + (16 + bRow2) * 72 + k0 + bKo2));    // nt 2
                mma_f16(accI[2], ai, b2);
            }
        }
    }
    __syncthreads();

    // ================= phase 2: hid -> smem, logits -> smem, softmax =========
    #pragma unroll
    for (int mt = 0; mt < 2; mt++) {
        #pragma unroll
        for (int nt = 0; nt < 9; nt++) {
            int col = n0 + nt * 8 + ((lane & 3) << 1);
            int rl = m0 + mt * 16 + (lane >> 2);
            #pragma unroll
            for (int h = 0; h < 2; h++) {
                float v0 = acc1[mt][nt][h * 2 + 0];
                float v1 = acc1[mt][nt][h * 2 + 1];
                if (col == 140) v0 = 1.f;      // ones column (b2)
                *(uint32_t*)(sHid + (rl + h * 8) * 152 + col) = pack2f(v0, v1);
            }
        }
    }
    #pragma unroll
    for (int nt = 0; nt < 3; nt++) {
        int col = nt * 8 + ((lane & 3) << 1);
        int rl = mI + (lane >> 2);
        sL[rl * 25 + col]           = accI[nt][0];
        sL[rl * 25 + col + 1]       = accI[nt][1];
        sL[(rl + 8) * 25 + col]     = accI[nt][2];
        sL[(rl + 8) * 25 + col + 1] = accI[nt][3];
    }
    __syncthreads();

    // stage W2 chunks 0,1 (overlaps softmax)
    stage_w2((__half*)(smem + SW2A), 0, tid);
    stage_w2((__half*)(smem + SW2B), 1, tid);

    // softmax over 32 agents, 4 frames per CTA, per logit column
    if (tid < 72) {
        int f = tid / 18, j = tid - f * 18;
        float vals[32], mx = -1e30f;
        #pragma unroll
        for (int a = 0; a < 32; a++) {
            vals[a] = sL[(f * 32 + a) * 25 + j];
            mx = fmaxf(mx, vals[a]);
        }
        float s = 0.f;
        #pragma unroll
        for (int a = 0; a < 32; a++) { vals[a] = expf(vals[a] - mx); s += vals[a]; }
        float inv = 1.f / s;
        int frame = blockIdx.x * 4 + f;
        if (j < 8) {
            size_t base = OFF_A0 + (size_t)(frame * 32) * 8 + j;
            #pragma unroll
            for (int a = 0; a < 32; a++) out[base + (size_t)a * 8] = vals[a] * inv;
        } else if (j < 14) {
            size_t base = OFF_A1 + (size_t)(frame * 32) * 6 + (j - 8);
            #pragma unroll
            for (int a = 0; a < 32; a++) out[base + (size_t)a * 6] = vals[a] * inv;
        } else {
            size_t base = OFF_A2 + (size_t)(frame * 32) * 4 + (j - 14);
            #pragma unroll
            for (int a = 0; a < 32; a++) out[base + (size_t)a * 4] = vals[a] * inv;
        }
    }
    __syncthreads();

    // ================= phase 3: gemm2, 64x32 warp tiles, 2 chunks in flight ==
    // warp (w): chunk = pair*2 + (w>>2), m-group = (w>>1)&1, n-group = w&1
    const int p3c = w >> 2;                    // chunk-within-pair
    const int p3m = ((w >> 1) & 1) * 64;       // 64-row group base
    const int p3n = (w & 1) * 32;              // 32-col group base
    for (int pair = 0; pair < 2; pair++) {
        if (pair) {
            __syncthreads();
            stage_w2((__half*)(smem + SW2A), 2, tid);
            stage_w2((__half*)(smem + SW2B), 3, tid);
            __syncthreads();
        }
        __half* sW2 = (__half*)(smem + (p3c ? SW2B : SW2A));
        const int chunk = pair * 2 + p3c;

        float acc[4][4][4];
        #pragma unroll
        for (int a = 0; a < 4; a++)
            #pragma unroll
            for (int b = 0; b < 4; b++)
                #pragma unroll
                for (int q = 0; q < 4; q++) acc[a][b][q] = 0.f;

        #pragma unroll
        for (int ks = 0; ks < 9; ks++) {
            int k0 = ks * 16;
            uint32_t a[4][4];
            #pragma unroll
            for (int mt = 0; mt < 4; mt++)
                ldsm_x4(a[mt], smaddr(sHid + (p3m + mt * 16 + aRow) * 152 + k0 + aKo));
            #pragma unroll
            for (int ntp = 0; ntp < 2; ntp++) {
                uint32_t b4[4];
                ldsm_x4(b4, smaddr(sW2 + (p3n + ntp * 16 + bRowP) * 152 + k0 + bKoP));
                #pragma unroll
                for (int mt = 0; mt < 4; mt++) {
                    mma_f16(acc[mt][2 * ntp],     a[mt], b4);
                    mma_f16(acc[mt][2 * ntp + 1], a[mt], b4 + 2);
                }
            }
        }

        #pragma unroll
        for (int mt = 0; mt < 4; mt++) {
            #pragma unroll
            for (int nt = 0; nt < 4; nt++) {
                int col = chunk * 64 + p3n + nt * 8 + ((lane & 3) << 1);
                int rb = row0 + p3m + mt * 16 + (lane >> 2);
                *(float2*)(out + (size_t)rb * OUT2 + col) =
                    make_float2(acc[mt][nt][0], acc[mt][nt][1]);
                *(float2*)(out + (size_t)(rb + 8) * OUT2 + col) =
                    make_float2(acc[mt][nt][2], acc[mt][nt][3]);
            }
        }
    }
}

// ----------------------------------------------------------------
extern "C" void kernel_launch(void* const* d_in, const int* in_sizes, int n_in,
                              void* d_out, int out_size)
{
    const float* cur  = (const float*)d_in[0];
    const float* nxt  = (const float*)d_in[1];
    const int*   acts = (const int*)  d_in[2];
    const float* W1   = (const float*)d_in[3];
    const float* b1   = (const float*)d_in[4];
    const float* W2   = (const float*)d_in[5];
    const float* b2   = (const float*)d_in[6];
    const float* Wi0  = (const float*)d_in[7];
    const float* Wi1  = (const float*)d_in[9];
    const float* Wi2  = (const float*)d_in[11];
    float* out = (float*)d_out;

    cudaFuncSetAttribute(fused_all, cudaFuncAttributeMaxDynamicSharedMemorySize, SM_TOTAL);

    prep_kernel<<<(N1P * K1P + 255) / 256, 256>>>(W1, b1, W2, b2, Wi0, Wi1, Wi2);
    fused_all<<<N_ROWS / 128, 256, SM_TOTAL>>>(cur, nxt, acts, out);
}

// round 12
// speedup vs baseline: 1.4488x; 1.4488x over previous
#include <cuda_runtime.h>
#include <cuda_fp16.h>
#include <stdint.h>
#include <math.h>

#define N_FRAMES 2048
#define N_AGENTS 32
#define N_ROWS 65536
#define FEAT 512
#define HID 140
#define OUT2 256

#define OFF_A0 (N_ROWS * OUT2)
#define OFF_A1 (OFF_A0 + N_ROWS * 8)
#define OFF_A2 (OFF_A1 + N_ROWS * 6)

// padded dims
#define K1P 576   // 512 feat + 18 onehot + bias@530 + pad
#define N1P 144   // 140 hid + ones@140 + pad
#define K2P 144
#define KIP 1024  // cur|next
#define NIP 24

// smem strides (halfs)
#define STA 72    // A tile (8B-aligned stores, ldsm conflict-free)
#define STB 88    // B1/Wi tiles (16B-aligned for cp.async, conflict-free)
#define STW 168   // W2 tile   (16B-aligned for cp.async, conflict-free)
#define STH 152   // hid tile

// single-fp16 transposed weights
__device__ __align__(16) __half g_w1t[N1P * K1P];     // [n][k]
__device__ __align__(16) __half g_wit[NIP * KIP];     // [n][k]
__device__ __align__(16) __half g_w2t[OUT2 * K2P];    // [n][k]

// ---------------------------------------------------------------- helpers
__device__ __forceinline__ uint32_t smaddr(const void* p) {
    return (uint32_t)__cvta_generic_to_shared(p);
}
__device__ __forceinline__ void ldsm_x4(uint32_t* r, uint32_t a) {
    asm volatile("ldmatrix.sync.aligned.m8n8.x4.shared.b16 {%0,%1,%2,%3}, [%4];"
        : "=r"(r[0]), "=r"(r[1]), "=r"(r[2]), "=r"(r[3]) : "r"(a));
}
__device__ __forceinline__ void ldsm_x2(uint32_t* r, uint32_t a) {
    asm volatile("ldmatrix.sync.aligned.m8n8.x2.shared.b16 {%0,%1}, [%2];"
        : "=r"(r[0]), "=r"(r[1]) : "r"(a));
}
__device__ __forceinline__ void mma_f16(float* d, const uint32_t* a, const uint32_t* b) {
    asm volatile("mma.sync.aligned.m16n8k16.row.col.f32.f16.f16.f32 "
        "{%0,%1,%2,%3}, {%4,%5,%6,%7}, {%8,%9}, {%0,%1,%2,%3};"
        : "+f"(d[0]), "+f"(d[1]), "+f"(d[2]), "+f"(d[3])
        : "r"(a[0]), "r"(a[1]), "r"(a[2]), "r"(a[3]), "r"(b[0]), "r"(b[1]));
}
__device__ __forceinline__ void cp_async16(uint32_t saddr, const void* gptr) {
    asm volatile("cp.async.cg.shared.global [%0], [%1], 16;"
        :: "r"(saddr), "l"(gptr));
}
#define CP_COMMIT() asm volatile("cp.async.commit_group;")
#define CP_WAIT1()  asm volatile("cp.async.wait_group 1;")
__device__ __forceinline__ uint32_t pack2h(__half a, __half b) {
    __half2 t; t.x = a; t.y = b;
    return *reinterpret_cast<uint32_t*>(&t);
}
__device__ __forceinline__ uint32_t pack2f(float a, float b) {
    return pack2h(__float2half_rn(a), __float2half_rn(b));
}

// ---------------------------------------------------------------- prep
__global__ void prep_kernel(
    const float* __restrict__ W1, const float* __restrict__ b1,
    const float* __restrict__ W2, const float* __restrict__ b2,
    const float* __restrict__ Wi0, const float* __restrict__ Wi1,
    const float* __restrict__ Wi2)
{
    int idx = blockIdx.x * 256 + threadIdx.x;
    if (idx < N1P * K1P) {
        int n = idx / K1P, k = idx - n * K1P;
        float v = 0.f;
        if (n < HID) {
            if (k < 530)       v = W1[(size_t)k * HID + n];
            else if (k == 530) v = b1[n];
        }
        g_w1t[idx] = __float2half_rn(v);
    }
    if (idx < OUT2 * K2P) {
        int n = idx / K2P, k = idx - n * K2P;
        float v = 0.f;
        if (k < HID)       v = W2[(size_t)k * OUT2 + n];
        else if (k == HID) v = b2[n];
        g_w2t[idx] = __float2half_rn(v);
    }
    if (idx < NIP * KIP) {
        int n = idx / KIP, k = idx - n * KIP;
        float v = 0.f;
        if (n < 8)        v = Wi0[(size_t)k * 8 + n];
        else if (n < 14)  v = Wi1[(size_t)k * 6 + (n - 8)];
        else if (n < 18)  v = Wi2[(size_t)k * 4 + (n - 14)];
        g_wit[idx] = __float2half_rn(v);
    }
}

// stage 128x64 fp32 feature chunk -> fp16 smem (stride 72 halfs)
__device__ __forceinline__ void stage_feat(
    __half* sA, const float* __restrict__ src, int row0, int c0, int tid)
{
    #pragma unroll
    for (int j = 0; j < 8; j++) {
        int i = tid + j * 256;
        int r = i >> 4, ce = (i & 15) << 2;
        float4 v = *(const float4*)(src + (size_t)(row0 + r) * FEAT + c0 + ce);
        uint2 u;
        u.x = pack2f(v.x, v.y);
        u.y = pack2f(v.z, v.w);
        *(uint2*)(sA + r * STA + ce) = u;
    }
}
// async weight staging (cp.async 16B, 16B-aligned strides)
__device__ __forceinline__ void stage_b1_async(uint32_t sB, int k64, int tid)
{
    #pragma unroll
    for (int j = 0; j < 5; j++) {
        int i = tid + j * 256;                 // 144*8 = 1152 chunks
        if (i < 1152) {
            int n = i >> 3, ce = (i & 7) << 3;
            cp_async16(sB + (uint32_t)(n * STB + ce) * 2,
                       g_w1t + (size_t)n * K1P + k64 + ce);
        }
    }
}
__device__ __forceinline__ void stage_wi_async(uint32_t sW, int k64, int tid)
{
    if (tid < 192) {                           // 24*8 chunks
        int n = tid >> 3, ce = (tid & 7) << 3;
        cp_async16(sW + (uint32_t)(n * STB + ce) * 2,
                   g_wit + (size_t)n * KIP + k64 + ce);
    }
}
__device__ __forceinline__ void stage_w2_async(uint32_t sW2, int c, int tid)
{
    #pragma unroll
    for (int j = 0; j < 5; j++) {
        int i = tid + j * 256;                 // 64*18 = 1152 chunks
        if (i < 1152) {
            int n = i / 18, t = i - n * 18;
            cp_async16(sW2 + (uint32_t)(n * STW + t * 8) * 2,
                       g_w2t + (size_t)(c * 64 + n) * K2P + t * 8);
        }
    }
}
// special chunk (one-hot + bias-one): thread r owns row r -> race-free
__device__ __forceinline__ void stage_special(
    __half* sA, const int* __restrict__ actions, int row0, int tid)
{
    if (tid < 128) {
        int r = tid;
        #pragma unroll
        for (int q = 0; q < 8; q++)
            *(uint4*)(sA + r * STA + q * 8) = make_uint4(0, 0, 0, 0);
        int f = (row0 + r) >> 5, ag = (row0 + r) & 31;
        int i0 = actions[(f * 3 + 0) * N_AGENTS + ag];
        int i1 = actions[(f * 3 + 1) * N_AGENTS + ag];
        int i2 = actions[(f * 3 + 2) * N_AGENTS + ag];
        __half one = __float2half_rn(1.f);
        sA[r * STA + i0] = one;
        sA[r * STA + 8 + i1] = one;
        sA[r * STA + 14 + i2] = one;
        sA[r * STA + 18] = one;                // b1 column (k=530)
    }
}

// ---------------------------------------------------------------- FUSED v6
// R6 structure exactly; weight staging moved to cp.async with prefetch-1
// double buffering (B1/Wi in phase 1, W2 in phase 3); inv reuses gemm1 A frags.
// smem layout (bytes):
//  phase1: sA @0 18432 | B1A @18432 25344 | B1B @43776 25344
//          WiA @69120 4224 | WiB @73344 4224 | sL @77568 12800  -> 90368
//  phase2/3 aliases: sHid @0 38912 | W2A @43776 21504 | W2B @65280 21504
#define SA0   0
#define SB1A  18432
#define SB1B  43776
#define SWIA  69120
#define SWIB  73344
#define SL    77568
#define SHID  0
#define SW2A  43776
#define SW2B  65280
#define SM_TOTAL 90368

__global__ __launch_bounds__(256, 2) void fused_all(
    const float* __restrict__ cur, const float* __restrict__ nxt,
    const int* __restrict__ actions, float* __restrict__ out)
{
    extern __shared__ char smem[];
    const uint32_t sbase = smaddr(smem);
    __half* sA  = (__half*)(smem + SA0);
    float*  sL  = (float*) (smem + SL);
    __half* sHid = (__half*)(smem + SHID);

    const int tid = threadIdx.x, lane = tid & 31, w = tid >> 5;
    const int row0 = blockIdx.x * 128;
    const int m0 = (w >> 1) * 32;              // gemm1 warp rows
    const int wodd = w & 1;                    // n-half selector
    const int n0 = wodd * 72;
    const int mI = w * 16;                     // inv rows (== m0 + wodd*16)
    const int l15 = lane & 15;
    const int aRow = lane & 15, aKo = (lane >> 4) << 3;  // A ldsm_x4 pieces
    const int bRow = l15 & 7,  bKo = (l15 >> 3) << 3;    // B ldsm_x2 pieces

    // ================= phase 1 =================
    float acc1[2][9][4];
    #pragma unroll
    for (int a = 0; a < 2; a++)
        #pragma unroll
        for (int b = 0; b < 9; b++)
            #pragma unroll
            for (int c = 0; c < 4; c++) acc1[a][b][c] = 0.f;
    float accI[3][4];
    #pragma unroll
    for (int b = 0; b < 3; b++)
        #pragma unroll
        for (int c = 0; c < 4; c++) accI[b][c] = 0.f;

    // prologue: async-stage chunk-0 weights, then A chunk 0
    stage_b1_async(sbase + SB1A, 0, tid);
    stage_wi_async(sbase + SWIA, 0, tid);
    CP_COMMIT();
    stage_feat(sA, cur, row0, 0, tid);

    for (int kb = 0; kb < 17; kb++) {
        if (kb) {
            __syncthreads();                   // compute(kb-1) done
            // prefetch weights for this chunk already done at kb-1; now
            // stage A(kb) and prefetch weights for kb+1
            const int nb = kb + 1;
            if (nb < 8)
                stage_b1_async(sbase + ((nb & 1) ? SB1B : SB1A), nb * 64, tid);
            else if (nb == 16)
                stage_b1_async(sbase + SB1A, 512, tid);
            if (nb < 16)
                stage_wi_async(sbase + ((nb & 1) ? SWIB : SWIA), nb * 64, tid);
            CP_COMMIT();
            if (kb < 8)       stage_feat(sA, cur, row0, kb * 64, tid);
            else if (kb < 16) stage_feat(sA, nxt, row0, (kb - 8) * 64, tid);
            else              stage_special(sA, actions, row0, tid);
        } else {
            // kb == 0: prefetch chunk-1 weights (A(0) already staged)
            stage_b1_async(sbase + SB1B, 64, tid);
            stage_wi_async(sbase + SWIB, 64, tid);
            CP_COMMIT();
        }
        CP_WAIT1();                            // chunk-kb weights landed
        __syncthreads();

        const bool g1 = (kb < 8) || (kb == 16);
        const bool iv = (kb < 16);
        __half* cB = (__half*)(smem + ((kb & 1) ? SB1B : SB1A));
        __half* cW = (__half*)(smem + ((kb & 1) ? SWIB : SWIA));

        const int kmax = (kb == 16) ? 2 : 4;
        for (int ks = 0; ks < kmax; ks++) {
            int k0 = ks * 16;
            uint32_t a[2][4];
            if (g1) {
                #pragma unroll
                for (int mt = 0; mt < 2; mt++)
                    ldsm_x4(a[mt], smaddr(sA + (m0 + mt * 16 + aRow) * STA + k0 + aKo));
                #pragma unroll
                for (int nt = 0; nt < 9; nt++) {
                    uint32_t b[2];
                    ldsm_x2(b, smaddr(cB + (n0 + nt * 8 + bRow) * STB + k0 + bKo));
                    mma_f16(acc1[0][nt], a[0], b);
                    mma_f16(acc1[1][nt], a[1], b);
                }
            } else {
                ldsm_x4(a[wodd], smaddr(sA + (mI + aRow) * STA + k0 + aKo));
            }
            if (iv) {
                const uint32_t* ai = a[wodd];  // inv rows == gemm1 rows half
                #pragma unroll
                for (int nt = 0; nt < 3; nt++) {
                    uint32_t b[2];
                    ldsm_x2(b, smaddr(cW + (nt * 8 + bRow) * STB + k0 + bKo));
                    mma_f16(accI[nt], ai, b);
                }
            }
        }
    }
    __syncthreads();

    // ================= phase 2: hid -> smem, logits -> smem, softmax =========
    #pragma unroll
    for (int mt = 0; mt < 2; mt++) {
        #pragma unroll
        for (int nt = 0; nt < 9; nt++) {
            int col = n0 + nt * 8 + ((lane & 3) << 1);
            int rl = m0 + mt * 16 + (lane >> 2);
            #pragma unroll
            for (int h = 0; h < 2; h++) {
                float v0 = acc1[mt][nt][h * 2 + 0];
                float v1 = acc1[mt][nt][h * 2 + 1];
                if (col == 140) v0 = 1.f;      // ones column (b2)
                *(uint32_t*)(sHid + (rl + h * 8) * STH + col) = pack2f(v0, v1);
            }
        }
    }
    #pragma unroll
    for (int nt = 0; nt < 3; nt++) {
        int col = nt * 8 + ((lane & 3) << 1);
        int rl = mI + (lane >> 2);
        sL[rl * 25 + col]           = accI[nt][0];
        sL[rl * 25 + col + 1]       = accI[nt][1];
        sL[(rl + 8) * 25 + col]     = accI[nt][2];
        sL[(rl + 8) * 25 + col + 1] = accI[nt][3];
    }
    __syncthreads();

    // prefetch W2 chunk 0 (W2A does not overlap live sL), overlaps softmax
    stage_w2_async(sbase + SW2A, 0, tid);
    CP_COMMIT();

    // softmax over 32 agents, 4 frames per CTA, per logit column
    if (tid < 72) {
        int f = tid / 18, j = tid - f * 18;
        float vals[32], mx = -1e30f;
        #pragma unroll
        for (int a = 0; a < 32; a++) {
            vals[a] = sL[(f * 32 + a) * 25 + j];
            mx = fmaxf(mx, vals[a]);
        }
        float s = 0.f;
        #pragma unroll
        for (int a = 0; a < 32; a++) { vals[a] = expf(vals[a] - mx); s += vals[a]; }
        float inv = 1.f / s;
        int frame = blockIdx.x * 4 + f;
        if (j < 8) {
            size_t base = OFF_A0 + (size_t)(frame * 32) * 8 + j;
            #pragma unroll
            for (int a = 0; a < 32; a++) out[base + (size_t)a * 8] = vals[a] * inv;
        } else if (j < 14) {
            size_t base = OFF_A1 + (size_t)(frame * 32) * 6 + (j - 8);
            #pragma unroll
            for (int a = 0; a < 32; a++) out[base + (size_t)a * 6] = vals[a] * inv;
        } else {
            size_t base = OFF_A2 + (size_t)(frame * 32) * 4 + (j - 14);
            #pragma unroll
            for (int a = 0; a < 32; a++) out[base + (size_t)a * 4] = vals[a] * inv;
        }
    }
    __syncthreads();   // softmax done (sL dead -> W2B region usable)

    // ================= phase 3: gemm2 from smem hid (cp.async W2 db) =========
    const int m2 = (w >> 1) * 32, n2 = (w & 1) * 32;
    for (int c = 0; c < 4; c++) {
        if (c) __syncthreads();                // compute(c-1) done
        if (c < 3)
            stage_w2_async(sbase + (((c + 1) & 1) ? SW2B : SW2A), c + 1, tid);
        CP_COMMIT();
        CP_WAIT1();                            // W2(c) landed
        __syncthreads();

        __half* cW2 = (__half*)(smem + ((c & 1) ? SW2B : SW2A));
        float acc[2][4][4];
        #pragma unroll
        for (int a = 0; a < 2; a++)
            #pragma unroll
            for (int b = 0; b < 4; b++)
                #pragma unroll
                for (int q = 0; q < 4; q++) acc[a][b][q] = 0.f;

        #pragma unroll
        for (int ks = 0; ks < 9; ks++) {
            int k0 = ks * 16;
            uint32_t a[2][4];
            #pragma unroll
            for (int mt = 0; mt < 2; mt++)
                ldsm_x4(a[mt], smaddr(sHid + (m2 + mt * 16 + aRow) * STH + k0 + aKo));
            #pragma unroll
            for (int nt = 0; nt < 4; nt++) {
                uint32_t b[2];
                ldsm_x2(b, smaddr(cW2 + (n2 + nt * 8 + bRow) * STW + k0 + bKo));
                mma_f16(acc[0][nt], a[0], b);
                mma_f16(acc[1][nt], a[1], b);
            }
        }

        #pragma unroll
        for (int mt = 0; mt < 2; mt++) {
            #pragma unroll
            for (int nt = 0; nt < 4; nt++) {
                int col = c * 64 + n2 + nt * 8 + ((lane & 3) << 1);
                int rb = row0 + m2 + mt * 16 + (lane >> 2);
                *(float2*)(out + (size_t)rb * OUT2 + col) =
                    make_float2(acc[mt][nt][0], acc[mt][nt][1]);
                *(float2*)(out + (size_t)(rb + 8) * OUT2 + col) =
                    make_float2(acc[mt][nt][2], acc[mt][nt][3]);
            }
        }
    }
}

// ----------------------------------------------------------------
extern "C" void kernel_launch(void* const* d_in, const int* in_sizes, int n_in,
                              void* d_out, int out_size)
{
    const float* cur  = (const float*)d_in[0];
    const float* nxt  = (const float*)d_in[1];
    const int*   acts = (const int*)  d_in[2];
    const float* W1   = (const float*)d_in[3];
    const float* b1   = (const float*)d_in[4];
    const float* W2   = (const float*)d_in[5];
    const float* b2   = (const float*)d_in[6];
    const float* Wi0  = (const float*)d_in[7];
    const float* Wi1  = (const float*)d_in[9];
    const float* Wi2  = (const float*)d_in[11];
    float* out = (float*)d_out;

    cudaFuncSetAttribute(fused_all, cudaFuncAttributeMaxDynamicSharedMemorySize, SM_TOTAL);

    prep_kernel<<<(N1P * K1P + 255) / 256, 256>>>(W1, b1, W2, b2, Wi0, Wi1, Wi2);
    fused_all<<<N_ROWS / 128, 256, SM_TOTAL>>>(cur, nxt, acts, out);
}

// round 13
// speedup vs baseline: 1.5200x; 1.0491x over previous
#include <cuda_runtime.h>
#include <cuda_fp16.h>
#include <stdint.h>
#include <math.h>

#define N_FRAMES 2048
#define N_AGENTS 32
#define N_ROWS 65536
#define FEAT 512
#define HID 140
#define OUT2 256

#define OFF_A0 (N_ROWS * OUT2)
#define OFF_A1 (OFF_A0 + N_ROWS * 8)
#define OFF_A2 (OFF_A1 + N_ROWS * 6)

// padded dims
#define K1P 576   // 512 feat + 18 onehot + bias@530 + pad
#define N1P 144   // 140 hid + ones@140 + pad
#define K2P 144
#define KIP 1024  // cur|next
#define NIP 24

// smem strides (halfs)
#define STA 72    // A tile
#define STB 88    // B1/Wi tiles (16B-aligned for cp.async)
#define STW 168   // W2 tile
#define STH 152   // hid tile

// single-fp16 transposed weights
__device__ __align__(16) __half g_w1t[N1P * K1P];     // [n][k]
__device__ __align__(16) __half g_wit[NIP * KIP];     // [n][k]
__device__ __align__(16) __half g_w2t[OUT2 * K2P];    // [n][k]

// ---------------------------------------------------------------- helpers
__device__ __forceinline__ uint32_t smaddr(const void* p) {
    return (uint32_t)__cvta_generic_to_shared(p);
}
__device__ __forceinline__ void ldsm_x4(uint32_t* r, uint32_t a) {
    asm volatile("ldmatrix.sync.aligned.m8n8.x4.shared.b16 {%0,%1,%2,%3}, [%4];"
        : "=r"(r[0]), "=r"(r[1]), "=r"(r[2]), "=r"(r[3]) : "r"(a));
}
__device__ __forceinline__ void ldsm_x2(uint32_t* r, uint32_t a) {
    asm volatile("ldmatrix.sync.aligned.m8n8.x2.shared.b16 {%0,%1}, [%2];"
        : "=r"(r[0]), "=r"(r[1]) : "r"(a));
}
__device__ __forceinline__ void mma_f16(float* d, const uint32_t* a, const uint32_t* b) {
    asm volatile("mma.sync.aligned.m16n8k16.row.col.f32.f16.f16.f32 "
        "{%0,%1,%2,%3}, {%4,%5,%6,%7}, {%8,%9}, {%0,%1,%2,%3};"
        : "+f"(d[0]), "+f"(d[1]), "+f"(d[2]), "+f"(d[3])
        : "r"(a[0]), "r"(a[1]), "r"(a[2]), "r"(a[3]), "r"(b[0]), "r"(b[1]));
}
__device__ __forceinline__ void cp_async16(uint32_t saddr, const void* gptr) {
    asm volatile("cp.async.cg.shared.global [%0], [%1], 16;"
        :: "r"(saddr), "l"(gptr));
}
#define CP_COMMIT() asm volatile("cp.async.commit_group;")
#define CP_WAIT1()  asm volatile("cp.async.wait_group 1;")
// single-instruction f32x2 -> packed f16x2
__device__ __forceinline__ uint32_t cvt2(float lo, float hi) {
    __half2 h = __floats2half2_rn(lo, hi);
    return *reinterpret_cast<uint32_t*>(&h);
}

// ---------------------------------------------------------------- prep
__global__ void prep_kernel(
    const float* __restrict__ W1, const float* __restrict__ b1,
    const float* __restrict__ W2, const float* __restrict__ b2,
    const float* __restrict__ Wi0, const float* __restrict__ Wi1,
    const float* __restrict__ Wi2)
{
    int idx = blockIdx.x * 256 + threadIdx.x;
    if (idx < N1P * K1P) {
        int n = idx / K1P, k = idx - n * K1P;
        float v = 0.f;
        if (n < HID) {
            if (k < 530)       v = W1[(size_t)k * HID + n];
            else if (k == 530) v = b1[n];
        }
        g_w1t[idx] = __float2half_rn(v);
    }
    if (idx < OUT2 * K2P) {
        int n = idx / K2P, k = idx - n * K2P;
        float v = 0.f;
        if (k < HID)       v = W2[(size_t)k * OUT2 + n];
        else if (k == HID) v = b2[n];
        g_w2t[idx] = __float2half_rn(v);
    }
    if (idx < NIP * KIP) {
        int n = idx / KIP, k = idx - n * KIP;
        float v = 0.f;
        if (n < 8)        v = Wi0[(size_t)k * 8 + n];
        else if (n < 14)  v = Wi1[(size_t)k * 6 + (n - 8)];
        else if (n < 18)  v = Wi2[(size_t)k * 4 + (n - 14)];
        g_wit[idx] = __float2half_rn(v);
    }
}

// stage 128x64 fp32 feature chunk -> fp16 smem (stride 72 halfs)
// per thread: 4 iters of (2x LDG.128, 4x cvt.f16x2, 1x STS.128)
__device__ __forceinline__ void stage_feat(
    __half* sA, const float* __restrict__ src, int row0, int c0, int tid)
{
    #pragma unroll
    for (int j = 0; j < 4; j++) {
        int i = tid + j * 256;                 // 128 rows x 8 col-groups
        int r = i >> 3, ce = (i & 7) << 3;     // 8 fp32 per thread
        const float4* p = (const float4*)(src + (size_t)(row0 + r) * FEAT + c0 + ce);
        float4 v0 = p[0], v1 = p[1];
        uint4 u = make_uint4(cvt2(v0.x, v0.y), cvt2(v0.z, v0.w),
                             cvt2(v1.x, v1.y), cvt2(v1.z, v1.w));
        *(uint4*)(sA + r * STA + ce) = u;      // byte addr r*144+ce*2, 16B aligned
    }
}
// async weight staging (cp.async 16B)
__device__ __forceinline__ void stage_b1_async(uint32_t sB, int k64, int tid)
{
    #pragma unroll
    for (int j = 0; j < 5; j++) {
        int i = tid + j * 256;                 // 144*8 = 1152 chunks
        if (i < 1152) {
            int n = i >> 3, ce = (i & 7) << 3;
            cp_async16(sB + (uint32_t)(n * STB + ce) * 2,
                       g_w1t + (size_t)n * K1P + k64 + ce);
        }
    }
}
__device__ __forceinline__ void stage_wi_async(uint32_t sW, int k64, int tid)
{
    if (tid < 192) {                           // 24*8 chunks
        int n = tid >> 3, ce = (tid & 7) << 3;
        cp_async16(sW + (uint32_t)(n * STB + ce) * 2,
                   g_wit + (size_t)n * KIP + k64 + ce);
    }
}
__device__ __forceinline__ void stage_w2_async(uint32_t sW2, int c, int tid)
{
    #pragma unroll
    for (int j = 0; j < 5; j++) {
        int i = tid + j * 256;                 // 64*18 = 1152 chunks
        if (i < 1152) {
            int n = i / 18, t = i - n * 18;
            cp_async16(sW2 + (uint32_t)(n * STW + t * 8) * 2,
                       g_w2t + (size_t)(c * 64 + n) * K2P + t * 8);
        }
    }
}
// special chunk (one-hot + bias-one): thread r owns row r -> race-free
__device__ __forceinline__ void stage_special(
    __half* sA, const int* __restrict__ actions, int row0, int tid)
{
    if (tid < 128) {
        int r = tid;
        #pragma unroll
        for (int q = 0; q < 8; q++)
            *(uint4*)(sA + r * STA + q * 8) = make_uint4(0, 0, 0, 0);
        int f = (row0 + r) >> 5, ag = (row0 + r) & 31;
        int i0 = actions[(f * 3 + 0) * N_AGENTS + ag];
        int i1 = actions[(f * 3 + 1) * N_AGENTS + ag];
        int i2 = actions[(f * 3 + 2) * N_AGENTS + ag];
        __half one = __float2half_rn(1.f);
        sA[r * STA + i0] = one;
        sA[r * STA + 8 + i1] = one;
        sA[r * STA + 14 + i2] = one;
        sA[r * STA + 18] = one;                // b1 column (k=530)
    }
}

// ---------------------------------------------------------------- FUSED v7
// R12 structure (cp.async weights, prefetch-1) + compressed A-staging
// (LDG.128x2 + cvt.f16x2 + STS.128) and cvt.f16x2 hid epilogue.
#define SA0   0
#define SB1A  18432
#define SB1B  43776
#define SWIA  69120
#define SWIB  73344
#define SL    77568
#define SHID  0
#define SW2A  43776
#define SW2B  65280
#define SM_TOTAL 90368

__global__ __launch_bounds__(256, 2) void fused_all(
    const float* __restrict__ cur, const float* __restrict__ nxt,
    const int* __restrict__ actions, float* __restrict__ out)
{
    extern __shared__ char smem[];
    const uint32_t sbase = smaddr(smem);
    __half* sA  = (__half*)(smem + SA0);
    float*  sL  = (float*) (smem + SL);
    __half* sHid = (__half*)(smem + SHID);

    const int tid = threadIdx.x, lane = tid & 31, w = tid >> 5;
    const int row0 = blockIdx.x * 128;
    const int m0 = (w >> 1) * 32;              // gemm1 warp rows
    const int wodd = w & 1;                    // n-half selector
    const int n0 = wodd * 72;
    const int mI = w * 16;                     // inv rows (== m0 + wodd*16)
    const int l15 = lane & 15;
    const int aRow = lane & 15, aKo = (lane >> 4) << 3;  // A ldsm_x4 pieces
    const int bRow = l15 & 7,  bKo = (l15 >> 3) << 3;    // B ldsm_x2 pieces

    // ================= phase 1 =================
    float acc1[2][9][4];
    #pragma unroll
    for (int a = 0; a < 2; a++)
        #pragma unroll
        for (int b = 0; b < 9; b++)
            #pragma unroll
            for (int c = 0; c < 4; c++) acc1[a][b][c] = 0.f;
    float accI[3][4];
    #pragma unroll
    for (int b = 0; b < 3; b++)
        #pragma unroll
        for (int c = 0; c < 4; c++) accI[b][c] = 0.f;

    // prologue: async-stage chunk-0 weights, then A chunk 0
    stage_b1_async(sbase + SB1A, 0, tid);
    stage_wi_async(sbase + SWIA, 0, tid);
    CP_COMMIT();
    stage_feat(sA, cur, row0, 0, tid);

    for (int kb = 0; kb < 17; kb++) {
        if (kb) {
            __syncthreads();                   // compute(kb-1) done
            const int nb = kb + 1;
            if (nb < 8)
                stage_b1_async(sbase + ((nb & 1) ? SB1B : SB1A), nb * 64, tid);
            else if (nb == 16)
                stage_b1_async(sbase + SB1A, 512, tid);
            if (nb < 16)
                stage_wi_async(sbase + ((nb & 1) ? SWIB : SWIA), nb * 64, tid);
            CP_COMMIT();
            if (kb < 8)       stage_feat(sA, cur, row0, kb * 64, tid);
            else if (kb < 16) stage_feat(sA, nxt, row0, (kb - 8) * 64, tid);
            else              stage_special(sA, actions, row0, tid);
        } else {
            stage_b1_async(sbase + SB1B, 64, tid);
            stage_wi_async(sbase + SWIB, 64, tid);
            CP_COMMIT();
        }
        CP_WAIT1();                            // chunk-kb weights landed
        __syncthreads();

        const bool g1 = (kb < 8) || (kb == 16);
        const bool iv = (kb < 16);
        __half* cB = (__half*)(smem + ((kb & 1) ? SB1B : SB1A));
        __half* cW = (__half*)(smem + ((kb & 1) ? SWIB : SWIA));

        const int kmax = (kb == 16) ? 2 : 4;
        for (int ks = 0; ks < kmax; ks++) {
            int k0 = ks * 16;
            uint32_t a[2][4];
            if (g1) {
                #pragma unroll
                for (int mt = 0; mt < 2; mt++)
                    ldsm_x4(a[mt], smaddr(sA + (m0 + mt * 16 + aRow) * STA + k0 + aKo));
                #pragma unroll
                for (int nt = 0; nt < 9; nt++) {
                    uint32_t b[2];
                    ldsm_x2(b, smaddr(cB + (n0 + nt * 8 + bRow) * STB + k0 + bKo));
                    mma_f16(acc1[0][nt], a[0], b);
                    mma_f16(acc1[1][nt], a[1], b);
                }
            } else {
                ldsm_x4(a[wodd], smaddr(sA + (mI + aRow) * STA + k0 + aKo));
            }
            if (iv) {
                const uint32_t* ai = a[wodd];  // inv rows == this warp's half
                #pragma unroll
                for (int nt = 0; nt < 3; nt++) {
                    uint32_t b[2];
                    ldsm_x2(b, smaddr(cW + (nt * 8 + bRow) * STB + k0 + bKo));
                    mma_f16(accI[nt], ai, b);
                }
            }
        }
    }
    __syncthreads();

    // ================= phase 2: hid -> smem, logits -> smem, softmax =========
    #pragma unroll
    for (int mt = 0; mt < 2; mt++) {
        #pragma unroll
        for (int nt = 0; nt < 9; nt++) {
            int col = n0 + nt * 8 + ((lane & 3) << 1);
            int rl = m0 + mt * 16 + (lane >> 2);
            #pragma unroll
            for (int h = 0; h < 2; h++) {
                float v0 = acc1[mt][nt][h * 2 + 0];
                float v1 = acc1[mt][nt][h * 2 + 1];
                if (col == 140) v0 = 1.f;      // ones column (b2)
                *(uint32_t*)(sHid + (rl + h * 8) * STH + col) = cvt2(v0, v1);
            }
        }
    }
    #pragma unroll
    for (int nt = 0; nt < 3; nt++) {
        int col = nt * 8 + ((lane & 3) << 1);
        int rl = mI + (lane >> 2);
        sL[rl * 25 + col]           = accI[nt][0];
        sL[rl * 25 + col + 1]       = accI[nt][1];
        sL[(rl + 8) * 25 + col]     = accI[nt][2];
        sL[(rl + 8) * 25 + col + 1] = accI[nt][3];
    }
    __syncthreads();

    // prefetch W2 chunk 0 (W2A does not overlap live sL), overlaps softmax
    stage_w2_async(sbase + SW2A, 0, tid);
    CP_COMMIT();

    // softmax over 32 agents, 4 frames per CTA, per logit column
    if (tid < 72) {
        int f = tid / 18, j = tid - f * 18;
        float vals[32], mx = -1e30f;
        #pragma unroll
        for (int a = 0; a < 32; a++) {
            vals[a] = sL[(f * 32 + a) * 25 + j];
            mx = fmaxf(mx, vals[a]);
        }
        float s = 0.f;
        #pragma unroll
        for (int a = 0; a < 32; a++) { vals[a] = expf(vals[a] - mx); s += vals[a]; }
        float inv = 1.f / s;
        int frame = blockIdx.x * 4 + f;
        if (j < 8) {
            size_t base = OFF_A0 + (size_t)(frame * 32) * 8 + j;
            #pragma unroll
            for (int a = 0; a < 32; a++) out[base + (size_t)a * 8] = vals[a] * inv;
        } else if (j < 14) {
            size_t base = OFF_A1 + (size_t)(frame * 32) * 6 + (j - 8);
            #pragma unroll
            for (int a = 0; a < 32; a++) out[base + (size_t)a * 6] = vals[a] * inv;
        } else {
            size_t base = OFF_A2 + (size_t)(frame * 32) * 4 + (j - 14);
            #pragma unroll
            for (int a = 0; a < 32; a++) out[base + (size_t)a * 4] = vals[a] * inv;
        }
    }
    __syncthreads();   // softmax done (sL dead -> W2B region usable)

    // ================= phase 3: gemm2 from smem hid (cp.async W2 db) =========
    const int m2 = (w >> 1) * 32, n2 = (w & 1) * 32;
    for (int c = 0; c < 4; c++) {
        if (c) __syncthreads();                // compute(c-1) done
        if (c < 3)
            stage_w2_async(sbase + (((c + 1) & 1) ? SW2B : SW2A), c + 1, tid);
        CP_COMMIT();
        CP_WAIT1();                            // W2(c) landed
        __syncthreads();

        __half* cW2 = (__half*)(smem + ((c & 1) ? SW2B : SW2A));
        float acc[2][4][4];
        #pragma unroll
        for (int a = 0; a < 2; a++)
            #pragma unroll
            for (int b = 0; b < 4; b++)
                #pragma unroll
                for (int q = 0; q < 4; q++) acc[a][b][q] = 0.f;

        #pragma unroll
        for (int ks = 0; ks < 9; ks++) {
            int k0 = ks * 16;
            uint32_t a[2][4];
            #pragma unroll
            for (int mt = 0; mt < 2; mt++)
                ldsm_x4(a[mt], smaddr(sHid + (m2 + mt * 16 + aRow) * STH + k0 + aKo));
            #pragma unroll
            for (int nt = 0; nt < 4; nt++) {
                uint32_t b[2];
                ldsm_x2(b, smaddr(cW2 + (n2 + nt * 8 + bRow) * STW + k0 + bKo));
                mma_f16(acc[0][nt], a[0], b);
                mma_f16(acc[1][nt], a[1], b);
            }
        }

        #pragma unroll
        for (int mt = 0; mt < 2; mt++) {
            #pragma unroll
            for (int nt = 0; nt < 4; nt++) {
                int col = c * 64 + n2 + nt * 8 + ((lane & 3) << 1);
                int rb = row0 + m2 + mt * 16 + (lane >> 2);
                *(float2*)(out + (size_t)rb * OUT2 + col) =
                    make_float2(acc[mt][nt][0], acc[mt][nt][1]);
                *(float2*)(out + (size_t)(rb + 8) * OUT2 + col) =
                    make_float2(acc[mt][nt][2], acc[mt][nt][3]);
            }
        }
    }
}

// ----------------------------------------------------------------
extern "C" void kernel_launch(void* const* d_in, const int* in_sizes, int n_in,
                              void* d_out, int out_size)
{
    const float* cur  = (const float*)d_in[0];
    const float* nxt  = (const float*)d_in[1];
    const int*   acts = (const int*)  d_in[2];
    const float* W1   = (const float*)d_in[3];
    const float* b1   = (const float*)d_in[4];
    const float* W2   = (const float*)d_in[5];
    const float* b2   = (const float*)d_in[6];
    const float* Wi0  = (const float*)d_in[7];
    const float* Wi1  = (const float*)d_in[9];
    const float* Wi2  = (const float*)d_in[11];
    float* out = (float*)d_out;

    cudaFuncSetAttribute(fused_all, cudaFuncAttributeMaxDynamicSharedMemorySize, SM_TOTAL);

    prep_kernel<<<(N1P * K1P + 255) / 256, 256>>>(W1, b1, W2, b2, Wi0, Wi1, Wi2);
    fused_all<<<N_ROWS / 128, 256, SM_TOTAL>>>(cur, nxt, acts, out);
}

// round 14
// speedup vs baseline: 1.6395x; 1.0786x over previous
#include <cuda_runtime.h>
#include <cuda_fp16.h>
#include <stdint.h>
#include <math.h>

#define N_FRAMES 2048
#define N_AGENTS 32
#define N_ROWS 65536
#define FEAT 512
#define HID 140
#define OUT2 256

#define OFF_A0 (N_ROWS * OUT2)
#define OFF_A1 (OFF_A0 + N_ROWS * 8)
#define OFF_A2 (OFF_A1 + N_ROWS * 6)

// padded dims
#define K1P 576   // 512 feat + 18 onehot + bias@530 + pad
#define N1P 144   // 140 hid + ones@140 + pad
#define K2P 144
#define KIP 1024  // cur|next
#define NIP 24

// smem strides (halfs)
#define STA 72    // A tiles
#define STB 88    // B1/Wi tiles (16B-aligned for cp.async)
#define STW 168   // W2 tile
#define STH 152   // hid tile

// single-fp16 transposed weights
__device__ __align__(16) __half g_w1t[N1P * K1P];     // [n][k]
__device__ __align__(16) __half g_wit[NIP * KIP];     // [n][k]
__device__ __align__(16) __half g_w2t[OUT2 * K2P];    // [n][k]

// ---------------------------------------------------------------- helpers
__device__ __forceinline__ uint32_t smaddr(const void* p) {
    return (uint32_t)__cvta_generic_to_shared(p);
}
__device__ __forceinline__ void ldsm_x4(uint32_t* r, uint32_t a) {
    asm volatile("ldmatrix.sync.aligned.m8n8.x4.shared.b16 {%0,%1,%2,%3}, [%4];"
        : "=r"(r[0]), "=r"(r[1]), "=r"(r[2]), "=r"(r[3]) : "r"(a));
}
__device__ __forceinline__ void ldsm_x2(uint32_t* r, uint32_t a) {
    asm volatile("ldmatrix.sync.aligned.m8n8.x2.shared.b16 {%0,%1}, [%2];"
        : "=r"(r[0]), "=r"(r[1]) : "r"(a));
}
__device__ __forceinline__ void mma_f16(float* d, const uint32_t* a, const uint32_t* b) {
    asm volatile("mma.sync.aligned.m16n8k16.row.col.f32.f16.f16.f32 "
        "{%0,%1,%2,%3}, {%4,%5,%6,%7}, {%8,%9}, {%0,%1,%2,%3};"
        : "+f"(d[0]), "+f"(d[1]), "+f"(d[2]), "+f"(d[3])
        : "r"(a[0]), "r"(a[1]), "r"(a[2]), "r"(a[3]), "r"(b[0]), "r"(b[1]));
}
__device__ __forceinline__ void cp_async16(uint32_t saddr, const void* gptr) {
    asm volatile("cp.async.cg.shared.global [%0], [%1], 16;"
        :: "r"(saddr), "l"(gptr));
}
#define CP_COMMIT() asm volatile("cp.async.commit_group;")
#define CP_WAIT0()  asm volatile("cp.async.wait_group 0;")
#define CP_WAIT1()  asm volatile("cp.async.wait_group 1;")
// single-instruction f32x2 -> packed f16x2
__device__ __forceinline__ uint32_t cvt2(float lo, float hi) {
    __half2 h = __floats2half2_rn(lo, hi);
    return *reinterpret_cast<uint32_t*>(&h);
}

// ---------------------------------------------------------------- prep
__global__ void prep_kernel(
    const float* __restrict__ W1, const float* __restrict__ b1,
    const float* __restrict__ W2, const float* __restrict__ b2,
    const float* __restrict__ Wi0, const float* __restrict__ Wi1,
    const float* __restrict__ Wi2)
{
    int idx = blockIdx.x * 256 + threadIdx.x;
    if (idx < N1P * K1P) {
        int n = idx / K1P, k = idx - n * K1P;
        float v = 0.f;
        if (n < HID) {
            if (k < 530)       v = W1[(size_t)k * HID + n];
            else if (k == 530) v = b1[n];
        }
        g_w1t[idx] = __float2half_rn(v);
    }
    if (idx < OUT2 * K2P) {
        int n = idx / K2P, k = idx - n * K2P;
        float v = 0.f;
        if (k < HID)       v = W2[(size_t)k * OUT2 + n];
        else if (k == HID) v = b2[n];
        g_w2t[idx] = __float2half_rn(v);
    }
    if (idx < NIP * KIP) {
        int n = idx / KIP, k = idx - n * KIP;
        float v = 0.f;
        if (n < 8)        v = Wi0[(size_t)k * 8 + n];
        else if (n < 14)  v = Wi1[(size_t)k * 6 + (n - 8)];
        else if (n < 18)  v = Wi2[(size_t)k * 4 + (n - 14)];
        g_wit[idx] = __float2half_rn(v);
    }
}

// stage 128x64 fp32 feature chunk -> fp16 smem (stride 72 halfs)
__device__ __forceinline__ void stage_feat(
    __half* sA, const float* __restrict__ src, int row0, int c0, int tid)
{
    #pragma unroll
    for (int j = 0; j < 4; j++) {
        int i = tid + j * 256;                 // 128 rows x 8 col-groups
        int r = i >> 3, ce = (i & 7) << 3;     // 8 fp32 per thread
        const float4* p = (const float4*)(src + (size_t)(row0 + r) * FEAT + c0 + ce);
        float4 v0 = p[0], v1 = p[1];
        uint4 u = make_uint4(cvt2(v0.x, v0.y), cvt2(v0.z, v0.w),
                             cvt2(v1.x, v1.y), cvt2(v1.z, v1.w));
        *(uint4*)(sA + r * STA + ce) = u;
    }
}
// async weight staging (cp.async 16B)
__device__ __forceinline__ void stage_b1_async(uint32_t sB, int k64, int tid)
{
    #pragma unroll
    for (int j = 0; j < 5; j++) {
        int i = tid + j * 256;                 // 144*8 = 1152 chunks
        if (i < 1152) {
            int n = i >> 3, ce = (i & 7) << 3;
            cp_async16(sB + (uint32_t)(n * STB + ce) * 2,
                       g_w1t + (size_t)n * K1P + k64 + ce);
        }
    }
}
__device__ __forceinline__ void stage_wi_async(uint32_t sW, int k64, int tid)
{
    if (tid < 192) {                           // 24*8 chunks
        int n = tid >> 3, ce = (tid & 7) << 3;
        cp_async16(sW + (uint32_t)(n * STB + ce) * 2,
                   g_wit + (size_t)n * KIP + k64 + ce);
    }
}
__device__ __forceinline__ void stage_w2_async(uint32_t sW2, int c, int tid)
{
    #pragma unroll
    for (int j = 0; j < 5; j++) {
        int i = tid + j * 256;                 // 64*18 = 1152 chunks
        if (i < 1152) {
            int n = i / 18, t = i - n * 18;
            cp_async16(sW2 + (uint32_t)(n * STW + t * 8) * 2,
                       g_w2t + (size_t)(c * 64 + n) * K2P + t * 8);
        }
    }
}
// special chunk (one-hot + bias-one): thread r owns row r -> race-free
__device__ __forceinline__ void stage_special(
    __half* sA, const int* __restrict__ actions, int row0, int tid)
{
    if (tid < 128) {
        int r = tid;
        #pragma unroll
        for (int q = 0; q < 8; q++)
            *(uint4*)(sA + r * STA + q * 8) = make_uint4(0, 0, 0, 0);
        int f = (row0 + r) >> 5, ag = (row0 + r) & 31;
        int i0 = actions[(f * 3 + 0) * N_AGENTS + ag];
        int i1 = actions[(f * 3 + 1) * N_AGENTS + ag];
        int i2 = actions[(f * 3 + 2) * N_AGENTS + ag];
        __half one = __float2half_rn(1.f);
        sA[r * STA + i0] = one;
        sA[r * STA + 8 + i1] = one;
        sA[r * STA + 14 + i2] = one;
        sA[r * STA + 18] = one;                // b1 column (k=530)
    }
}

// ---------------------------------------------------------------- FUSED v8
// Merged cur+nxt mainloop: 9 iterations (8 merged + special) instead of 17.
// Each iteration stages A_cur(kb), A_nxt(kb), B1(kb), Wi_cur(kb), Wi_nxt(kb)
// (weights via cp.async) and computes gemm1 + inv(cur) + inv(nxt).
// smem phase1 (bytes):
//   A_cur @0 18432 | A_nxt @18432 18432 | B1 @36864 25344
//   WiC @62208 4224 | WiN @66432 4224 | sL @70656 12800   total 83456
// phase2/3 aliases: sHid @0 38912 | W2A @39168 21504 | W2B @60672 21504
//   (W2B overlaps sL but is only staged after softmax completes)
#define SAC   0
#define SAN   18432
#define SB1   36864
#define SWC   62208
#define SWN   66432
#define SL    70656
#define SHID  0
#define SW2A  39168
#define SW2B  60672
#define SM_TOTAL 83456

__global__ __launch_bounds__(256, 2) void fused_all(
    const float* __restrict__ cur, const float* __restrict__ nxt,
    const int* __restrict__ actions, float* __restrict__ out)
{
    extern __shared__ char smem[];
    const uint32_t sbase = smaddr(smem);
    __half* sAc = (__half*)(smem + SAC);
    __half* sAn = (__half*)(smem + SAN);
    __half* sB1 = (__half*)(smem + SB1);
    __half* sWc = (__half*)(smem + SWC);
    __half* sWn = (__half*)(smem + SWN);
    float*  sL  = (float*) (smem + SL);
    __half* sHid = (__half*)(smem + SHID);

    const int tid = threadIdx.x, lane = tid & 31, w = tid >> 5;
    const int row0 = blockIdx.x * 128;
    const int m0 = (w >> 1) * 32;              // gemm1 warp rows
    const int wodd = w & 1;                    // n-half selector
    const int n0 = wodd * 72;
    const int mI = w * 16;                     // inv rows (== m0 + wodd*16)
    const int l15 = lane & 15;
    const int aRow = lane & 15, aKo = (lane >> 4) << 3;  // A ldsm_x4 pieces
    const int bRow = l15 & 7,  bKo = (l15 >> 3) << 3;    // B ldsm_x2 pieces

    // ================= phase 1: merged mainloop =================
    float acc1[2][9][4];
    #pragma unroll
    for (int a = 0; a < 2; a++)
        #pragma unroll
        for (int b = 0; b < 9; b++)
            #pragma unroll
            for (int c = 0; c < 4; c++) acc1[a][b][c] = 0.f;
    float accI[3][4];
    #pragma unroll
    for (int b = 0; b < 3; b++)
        #pragma unroll
        for (int c = 0; c < 4; c++) accI[b][c] = 0.f;

    for (int kb = 0; kb < 9; kb++) {
        if (kb) __syncthreads();               // compute(kb-1) done

        // ---- stage everything for this iteration
        if (kb < 8) {
            stage_wi_async(sbase + SWC, kb * 64, tid);
            stage_wi_async(sbase + SWN, 512 + kb * 64, tid);
            stage_b1_async(sbase + SB1, kb * 64, tid);
            CP_COMMIT();
            stage_feat(sAc, cur, row0, kb * 64, tid);
            stage_feat(sAn, nxt, row0, kb * 64, tid);
        } else {
            stage_b1_async(sbase + SB1, 512, tid);
            CP_COMMIT();
            stage_special(sAc, actions, row0, tid);
        }
        CP_WAIT0();
        __syncthreads();

        // ---- compute
        const bool iv = (kb < 8);
        const int kmax = (kb == 8) ? 2 : 4;
        for (int ks = 0; ks < kmax; ks++) {
            int k0 = ks * 16;
            uint32_t a[2][4];
            #pragma unroll
            for (int mt = 0; mt < 2; mt++)
                ldsm_x4(a[mt], smaddr(sAc + (m0 + mt * 16 + aRow) * STA + k0 + aKo));
            #pragma unroll
            for (int nt = 0; nt < 9; nt++) {
                uint32_t b[2];
                ldsm_x2(b, smaddr(sB1 + (n0 + nt * 8 + bRow) * STB + k0 + bKo));
                mma_f16(acc1[0][nt], a[0], b);
                mma_f16(acc1[1][nt], a[1], b);
            }
            if (iv) {
                // inv over cur-half: reuse this warp's gemm1 A fragment
                const uint32_t* ai = a[wodd];
                #pragma unroll
                for (int nt = 0; nt < 3; nt++) {
                    uint32_t b[2];
                    ldsm_x2(b, smaddr(sWc + (nt * 8 + bRow) * STB + k0 + bKo));
                    mma_f16(accI[nt], ai, b);
                }
                // inv over nxt-half
                uint32_t an[4];
                ldsm_x4(an, smaddr(sAn + (mI + aRow) * STA + k0 + aKo));
                #pragma unroll
                for (int nt = 0; nt < 3; nt++) {
                    uint32_t b[2];
                    ldsm_x2(b, smaddr(sWn + (nt * 8 + bRow) * STB + k0 + bKo));
                    mma_f16(accI[nt], an, b);
                }
            }
        }
    }
    __syncthreads();

    // ================= phase 2: hid -> smem, logits -> smem, softmax =========
    #pragma unroll
    for (int mt = 0; mt < 2; mt++) {
        #pragma unroll
        for (int nt = 0; nt < 9; nt++) {
            int col = n0 + nt * 8 + ((lane & 3) << 1);
            int rl = m0 + mt * 16 + (lane >> 2);
            #pragma unroll
            for (int h = 0; h < 2; h++) {
                float v0 = acc1[mt][nt][h * 2 + 0];
                float v1 = acc1[mt][nt][h * 2 + 1];
                if (col == 140) v0 = 1.f;      // ones column (b2)
                *(uint32_t*)(sHid + (rl + h * 8) * STH + col) = cvt2(v0, v1);
            }
        }
    }
    #pragma unroll
    for (int nt = 0; nt < 3; nt++) {
        int col = nt * 8 + ((lane & 3) << 1);
        int rl = mI + (lane >> 2);
        sL[rl * 25 + col]           = accI[nt][0];
        sL[rl * 25 + col + 1]       = accI[nt][1];
        sL[(rl + 8) * 25 + col]     = accI[nt][2];
        sL[(rl + 8) * 25 + col + 1] = accI[nt][3];
    }
    __syncthreads();

    // prefetch W2 chunk 0 (W2A does not overlap live sL), overlaps softmax
    stage_w2_async(sbase + SW2A, 0, tid);
    CP_COMMIT();

    // softmax over 32 agents, 4 frames per CTA, per logit column
    if (tid < 72) {
        int f = tid / 18, j = tid - f * 18;
        float vals[32], mx = -1e30f;
        #pragma unroll
        for (int a = 0; a < 32; a++) {
            vals[a] = sL[(f * 32 + a) * 25 + j];
            mx = fmaxf(mx, vals[a]);
        }
        float s = 0.f;
        #pragma unroll
        for (int a = 0; a < 32; a++) { vals[a] = expf(vals[a] - mx); s += vals[a]; }
        float inv = 1.f / s;
        int frame = blockIdx.x * 4 + f;
        if (j < 8) {
            size_t base = OFF_A0 + (size_t)(frame * 32) * 8 + j;
            #pragma unroll
            for (int a = 0; a < 32; a++) out[base + (size_t)a * 8] = vals[a] * inv;
        } else if (j < 14) {
            size_t base = OFF_A1 + (size_t)(frame * 32) * 6 + (j - 8);
            #pragma unroll
            for (int a = 0; a < 32; a++) out[base + (size_t)a * 6] = vals[a] * inv;
        } else {
            size_t base = OFF_A2 + (size_t)(frame * 32) * 4 + (j - 14);
            #pragma unroll
            for (int a = 0; a < 32; a++) out[base + (size_t)a * 4] = vals[a] * inv;
        }
    }
    __syncthreads();   // softmax done (sL dead -> W2B region usable)

    // ================= phase 3: gemm2 from smem hid (cp.async W2 db) =========
    const int m2 = (w >> 1) * 32, n2 = (w & 1) * 32;
    for (int c = 0; c < 4; c++) {
        if (c) __syncthreads();                // compute(c-1) done
        if (c < 3)
            stage_w2_async(sbase + (((c + 1) & 1) ? SW2B : SW2A), c + 1, tid);
        CP_COMMIT();
        CP_WAIT1();                            // W2(c) landed
        __syncthreads();

        __half* cW2 = (__half*)(smem + ((c & 1) ? SW2B : SW2A));
        float acc[2][4][4];
        #pragma unroll
        for (int a = 0; a < 2; a++)
            #pragma unroll
            for (int b = 0; b < 4; b++)
                #pragma unroll
                for (int q = 0; q < 4; q++) acc[a][b][q] = 0.f;

        #pragma unroll
        for (int ks = 0; ks < 9; ks++) {
            int k0 = ks * 16;
            uint32_t a[2][4];
            #pragma unroll
            for (int mt = 0; mt < 2; mt++)
                ldsm_x4(a[mt], smaddr(sHid + (m2 + mt * 16 + aRow) * STH + k0 + aKo));
            #pragma unroll
            for (int nt = 0; nt < 4; nt++) {
                uint32_t b[2];
                ldsm_x2(b, smaddr(cW2 + (n2 + nt * 8 + bRow) * STW + k0 + bKo));
                mma_f16(acc[0][nt], a[0], b);
                mma_f16(acc[1][nt], a[1], b);
            }
        }

        #pragma unroll
        for (int mt = 0; mt < 2; mt++) {
            #pragma unroll
            for (int nt = 0; nt < 4; nt++) {
                int col = c * 64 + n2 + nt * 8 + ((lane & 3) << 1);
                int rb = row0 + m2 + mt * 16 + (lane >> 2);
                *(float2*)(out + (size_t)rb * OUT2 + col) =
                    make_float2(acc[mt][nt][0], acc[mt][nt][1]);
                *(float2*)(out + (size_t)(rb + 8) * OUT2 + col) =
                    make_float2(acc[mt][nt][2], acc[mt][nt][3]);
            }
        }
    }
}

// ----------------------------------------------------------------
extern "C" void kernel_launch(void* const* d_in, const int* in_sizes, int n_in,
                              void* d_out, int out_size)
{
    const float* cur  = (const float*)d_in[0];
    const float* nxt  = (const float*)d_in[1];
    const int*   acts = (const int*)  d_in[2];
    const float* W1   = (const float*)d_in[3];
    const float* b1   = (const float*)d_in[4];
    const float* W2   = (const float*)d_in[5];
    const float* b2   = (const float*)d_in[6];
    const float* Wi0  = (const float*)d_in[7];
    const float* Wi1  = (const float*)d_in[9];
    const float* Wi2  = (const float*)d_in[11];
    float* out = (float*)d_out;

    cudaFuncSetAttribute(fused_all, cudaFuncAttributeMaxDynamicSharedMemorySize, SM_TOTAL);

    prep_kernel<<<(N1P * K1P + 255) / 256, 256>>>(W1, b1, W2, b2, Wi0, Wi1, Wi2);
    fused_all<<<N_ROWS / 128, 256, SM_TOTAL>>>(cur, nxt, acts, out);
}

// round 15
// speedup vs baseline: 1.8812x; 1.1474x over previous
#include <cuda_runtime.h>
#include <cuda_fp16.h>
#include <stdint.h>
#include <math.h>

#define N_FRAMES 2048
#define N_AGENTS 32
#define N_ROWS 65536
#define FEAT 512
#define HID 140
#define OUT2 256

#define OFF_A0 (N_ROWS * OUT2)
#define OFF_A1 (OFF_A0 + N_ROWS * 8)
#define OFF_A2 (OFF_A1 + N_ROWS * 6)

// padded dims
#define K1P 576   // 512 feat + 18 onehot + bias@530 + pad
#define N1P 144   // 140 hid + ones@140 + pad
#define K2P 144
#define KIP 1024  // cur|next
#define NIP 24

// smem strides (halfs) — 72*2=144B and 152*2=304B are 16B-aligned rows,
// bank-conflict-free for ldsm (proven layouts from R6).
#define STA 72    // A tiles
#define STB 72    // B1/Wi tiles
#define STW 152   // W2 tile
#define STH 152   // hid tile

// single-fp16 transposed weights
__device__ __align__(16) __half g_w1t[N1P * K1P];     // [n][k]
__device__ __align__(16) __half g_wit[NIP * KIP];     // [n][k]
__device__ __align__(16) __half g_w2t[OUT2 * K2P];    // [n][k]

// ---------------------------------------------------------------- helpers
__device__ __forceinline__ uint32_t smaddr(const void* p) {
    return (uint32_t)__cvta_generic_to_shared(p);
}
__device__ __forceinline__ void ldsm_x4(uint32_t* r, uint32_t a) {
    asm volatile("ldmatrix.sync.aligned.m8n8.x4.shared.b16 {%0,%1,%2,%3}, [%4];"
        : "=r"(r[0]), "=r"(r[1]), "=r"(r[2]), "=r"(r[3]) : "r"(a));
}
__device__ __forceinline__ void ldsm_x2(uint32_t* r, uint32_t a) {
    asm volatile("ldmatrix.sync.aligned.m8n8.x2.shared.b16 {%0,%1}, [%2];"
        : "=r"(r[0]), "=r"(r[1]) : "r"(a));
}
__device__ __forceinline__ void mma_f16(float* d, const uint32_t* a, const uint32_t* b) {
    asm volatile("mma.sync.aligned.m16n8k16.row.col.f32.f16.f16.f32 "
        "{%0,%1,%2,%3}, {%4,%5,%6,%7}, {%8,%9}, {%0,%1,%2,%3};"
        : "+f"(d[0]), "+f"(d[1]), "+f"(d[2]), "+f"(d[3])
        : "r"(a[0]), "r"(a[1]), "r"(a[2]), "r"(a[3]), "r"(b[0]), "r"(b[1]));
}
__device__ __forceinline__ void cp_async16(uint32_t saddr, const void* gptr) {
    asm volatile("cp.async.cg.shared.global [%0], [%1], 16;"
        :: "r"(saddr), "l"(gptr));
}
#define CP_COMMIT() asm volatile("cp.async.commit_group;")
#define CP_WAIT0()  asm volatile("cp.async.wait_group 0;")
#define CP_WAIT1()  asm volatile("cp.async.wait_group 1;")
__device__ __forceinline__ void prefetch_l2(const void* p) {
    asm volatile("prefetch.global.L2 [%0];" :: "l"(p));
}
// single-instruction f32x2 -> packed f16x2
__device__ __forceinline__ uint32_t cvt2(float lo, float hi) {
    __half2 h = __floats2half2_rn(lo, hi);
    return *reinterpret_cast<uint32_t*>(&h);
}

// ---------------------------------------------------------------- prep
__global__ void prep_kernel(
    const float* __restrict__ W1, const float* __restrict__ b1,
    const float* __restrict__ W2, const float* __restrict__ b2,
    const float* __restrict__ Wi0, const float* __restrict__ Wi1,
    const float* __restrict__ Wi2)
{
    int idx = blockIdx.x * 256 + threadIdx.x;
    if (idx < N1P * K1P) {
        int n = idx / K1P, k = idx - n * K1P;
        float v = 0.f;
        if (n < HID) {
            if (k < 530)       v = W1[(size_t)k * HID + n];
            else if (k == 530) v = b1[n];
        }
        g_w1t[idx] = __float2half_rn(v);
    }
    if (idx < OUT2 * K2P) {
        int n = idx / K2P, k = idx - n * K2P;
        float v = 0.f;
        if (k < HID)       v = W2[(size_t)k * OUT2 + n];
        else if (k == HID) v = b2[n];
        g_w2t[idx] = __float2half_rn(v);
    }
    if (idx < NIP * KIP) {
        int n = idx / KIP, k = idx - n * KIP;
        float v = 0.f;
        if (n < 8)        v = Wi0[(size_t)k * 8 + n];
        else if (n < 14)  v = Wi1[(size_t)k * 6 + (n - 8)];
        else if (n < 18)  v = Wi2[(size_t)k * 4 + (n - 14)];
        g_wit[idx] = __float2half_rn(v);
    }
}

// stage 128x64 fp32 feature chunk -> fp16 smem (stride 72 halfs)
__device__ __forceinline__ void stage_feat(
    __half* sA, const float* __restrict__ src, int row0, int c0, int tid)
{
    #pragma unroll
    for (int j = 0; j < 4; j++) {
        int i = tid + j * 256;                 // 128 rows x 8 col-groups
        int r = i >> 3, ce = (i & 7) << 3;     // 8 fp32 per thread
        const float4* p = (const float4*)(src + (size_t)(row0 + r) * FEAT + c0 + ce);
        float4 v0 = p[0], v1 = p[1];
        uint4 u = make_uint4(cvt2(v0.x, v0.y), cvt2(v0.z, v0.w),
                             cvt2(v1.x, v1.y), cvt2(v1.z, v1.w));
        *(uint4*)(sA + r * STA + ce) = u;
    }
}
// L2-prefetch the addresses stage_feat will LDG next iteration
__device__ __forceinline__ void prefetch_feat(
    const float* __restrict__ src, int row0, int c0, int tid)
{
    #pragma unroll
    for (int j = 0; j < 4; j++) {
        int i = tid + j * 256;
        int r = i >> 3, ce = (i & 7) << 3;
        prefetch_l2(src + (size_t)(row0 + r) * FEAT + c0 + ce);
    }
}
// async weight staging (cp.async 16B)
__device__ __forceinline__ void stage_b1_async(uint32_t sB, int k64, int tid)
{
    #pragma unroll
    for (int j = 0; j < 5; j++) {
        int i = tid + j * 256;                 // 144*8 = 1152 chunks
        if (i < 1152) {
            int n = i >> 3, ce = (i & 7) << 3;
            cp_async16(sB + (uint32_t)(n * STB + ce) * 2,
                       g_w1t + (size_t)n * K1P + k64 + ce);
        }
    }
}
__device__ __forceinline__ void stage_wi_async(uint32_t sW, int k64, int tid)
{
    if (tid < 192) {                           // 24*8 chunks
        int n = tid >> 3, ce = (tid & 7) << 3;
        cp_async16(sW + (uint32_t)(n * STB + ce) * 2,
                   g_wit + (size_t)n * KIP + k64 + ce);
    }
}
__device__ __forceinline__ void stage_w2_async(uint32_t sW2, int c, int tid)
{
    #pragma unroll
    for (int j = 0; j < 5; j++) {
        int i = tid + j * 256;                 // 64*18 = 1152 chunks
        if (i < 1152) {
            int n = i / 18, t = i - n * 18;
            cp_async16(sW2 + (uint32_t)(n * STW + t * 8) * 2,
                       g_w2t + (size_t)(c * 64 + n) * K2P + t * 8);
        }
    }
}
// special chunk (one-hot + bias-one): thread r owns row r -> race-free
__device__ __forceinline__ void stage_special(
    __half* sA, const int* __restrict__ actions, int row0, int tid)
{
    if (tid < 128) {
        int r = tid;
        #pragma unroll
        for (int q = 0; q < 8; q++)
            *(uint4*)(sA + r * STA + q * 8) = make_uint4(0, 0, 0, 0);
        int f = (row0 + r) >> 5, ag = (row0 + r) & 31;
        int i0 = actions[(f * 3 + 0) * N_AGENTS + ag];
        int i1 = actions[(f * 3 + 1) * N_AGENTS + ag];
        int i2 = actions[(f * 3 + 2) * N_AGENTS + ag];
        __half one = __float2half_rn(1.f);
        sA[r * STA + i0] = one;
        sA[r * STA + 8 + i1] = one;
        sA[r * STA + 14 + i2] = one;
        sA[r * STA + 18] = one;                // b1 column (k=530)
    }
}

// ---------------------------------------------------------------- FUSED v9
// R14 merged mainloop (9 iterations) + L2 prefetch of next A chunk during
// compute + tighter smem strides.
// smem phase1 (bytes):
//   A_cur @0 18432 | A_nxt @18432 18432 | B1 @36864 20736
//   WiC @57600 3456 | WiN @61056 3456 | sL @64512 12800   total 77312
// phase2/3 aliases: sHid @0 38912 | W2A @39168 19456 | W2B @58624 19456
//   (W2B overlaps sL but is only staged after softmax completes)
#define SAC   0
#define SAN   18432
#define SB1   36864
#define SWC   57600
#define SWN   61056
#define SL    64512
#define SHID  0
#define SW2A  39168
#define SW2B  58624
#define SM_TOTAL 78080

__global__ __launch_bounds__(256, 2) void fused_all(
    const float* __restrict__ cur, const float* __restrict__ nxt,
    const int* __restrict__ actions, float* __restrict__ out)
{
    extern __shared__ char smem[];
    const uint32_t sbase = smaddr(smem);
    __half* sAc = (__half*)(smem + SAC);
    __half* sAn = (__half*)(smem + SAN);
    __half* sB1 = (__half*)(smem + SB1);
    __half* sWc = (__half*)(smem + SWC);
    __half* sWn = (__half*)(smem + SWN);
    float*  sL  = (float*) (smem + SL);
    __half* sHid = (__half*)(smem + SHID);

    const int tid = threadIdx.x, lane = tid & 31, w = tid >> 5;
    const int row0 = blockIdx.x * 128;
    const int m0 = (w >> 1) * 32;              // gemm1 warp rows
    const int wodd = w & 1;                    // n-half selector
    const int n0 = wodd * 72;
    const int mI = w * 16;                     // inv rows (== m0 + wodd*16)
    const int l15 = lane & 15;
    const int aRow = lane & 15, aKo = (lane >> 4) << 3;  // A ldsm_x4 pieces
    const int bRow = l15 & 7,  bKo = (l15 >> 3) << 3;    // B ldsm_x2 pieces

    // ================= phase 1: merged mainloop =================
    float acc1[2][9][4];
    #pragma unroll
    for (int a = 0; a < 2; a++)
        #pragma unroll
        for (int b = 0; b < 9; b++)
            #pragma unroll
            for (int c = 0; c < 4; c++) acc1[a][b][c] = 0.f;
    float accI[3][4];
    #pragma unroll
    for (int b = 0; b < 3; b++)
        #pragma unroll
        for (int c = 0; c < 4; c++) accI[b][c] = 0.f;

    for (int kb = 0; kb < 9; kb++) {
        if (kb) __syncthreads();               // compute(kb-1) done

        // ---- stage everything for this iteration
        if (kb < 8) {
            stage_wi_async(sbase + SWC, kb * 64, tid);
            stage_wi_async(sbase + SWN, 512 + kb * 64, tid);
            stage_b1_async(sbase + SB1, kb * 64, tid);
            CP_COMMIT();
            stage_feat(sAc, cur, row0, kb * 64, tid);
            stage_feat(sAn, nxt, row0, kb * 64, tid);
        } else {
            stage_b1_async(sbase + SB1, 512, tid);
            CP_COMMIT();
            stage_special(sAc, actions, row0, tid);
        }
        CP_WAIT0();
        __syncthreads();

        // ---- L2-prefetch next chunk's A data (lands during compute below)
        if (kb < 7) {
            prefetch_feat(cur, row0, (kb + 1) * 64, tid);
            prefetch_feat(nxt, row0, (kb + 1) * 64, tid);
        }

        // ---- compute
        const bool iv = (kb < 8);
        const int kmax = (kb == 8) ? 2 : 4;
        for (int ks = 0; ks < kmax; ks++) {
            int k0 = ks * 16;
            uint32_t a[2][4];
            #pragma unroll
            for (int mt = 0; mt < 2; mt++)
                ldsm_x4(a[mt], smaddr(sAc + (m0 + mt * 16 + aRow) * STA + k0 + aKo));
            #pragma unroll
            for (int nt = 0; nt < 9; nt++) {
                uint32_t b[2];
                ldsm_x2(b, smaddr(sB1 + (n0 + nt * 8 + bRow) * STB + k0 + bKo));
                mma_f16(acc1[0][nt], a[0], b);
                mma_f16(acc1[1][nt], a[1], b);
            }
            if (iv) {
                // inv over cur-half: reuse this warp's gemm1 A fragment
                const uint32_t* ai = a[wodd];
                #pragma unroll
                for (int nt = 0; nt < 3; nt++) {
                    uint32_t b[2];
                    ldsm_x2(b, smaddr(sWc + (nt * 8 + bRow) * STB + k0 + bKo));
                    mma_f16(accI[nt], ai, b);
                }
                // inv over nxt-half
                uint32_t an[4];
                ldsm_x4(an, smaddr(sAn + (mI + aRow) * STA + k0 + aKo));
                #pragma unroll
                for (int nt = 0; nt < 3; nt++) {
                    uint32_t b[2];
                    ldsm_x2(b, smaddr(sWn + (nt * 8 + bRow) * STB + k0 + bKo));
                    mma_f16(accI[nt], an, b);
                }
            }
        }
    }
    __syncthreads();

    // ================= phase 2: hid -> smem, logits -> smem, softmax =========
    #pragma unroll
    for (int mt = 0; mt < 2; mt++) {
        #pragma unroll
        for (int nt = 0; nt < 9; nt++) {
            int col = n0 + nt * 8 + ((lane & 3) << 1);
            int rl = m0 + mt * 16 + (lane >> 2);
            #pragma unroll
            for (int h = 0; h < 2; h++) {
                float v0 = acc1[mt][nt][h * 2 + 0];
                float v1 = acc1[mt][nt][h * 2 + 1];
                if (col == 140) v0 = 1.f;      // ones column (b2)
                *(uint32_t*)(sHid + (rl + h * 8) * STH + col) = cvt2(v0, v1);
            }
        }
    }
    #pragma unroll
    for (int nt = 0; nt < 3; nt++) {
        int col = nt * 8 + ((lane & 3) << 1);
        int rl = mI + (lane >> 2);
        sL[rl * 25 + col]           = accI[nt][0];
        sL[rl * 25 + col + 1]       = accI[nt][1];
        sL[(rl + 8) * 25 + col]     = accI[nt][2];
        sL[(rl + 8) * 25 + col + 1] = accI[nt][3];
    }
    __syncthreads();

    // prefetch W2 chunk 0 (W2A does not overlap live sL), overlaps softmax
    stage_w2_async(sbase + SW2A, 0, tid);
    CP_COMMIT();

    // softmax over 32 agents, 4 frames per CTA, per logit column
    if (tid < 72) {
        int f = tid / 18, j = tid - f * 18;
        float vals[32], mx = -1e30f;
        #pragma unroll
        for (int a = 0; a < 32; a++) {
            vals[a] = sL[(f * 32 + a) * 25 + j];
            mx = fmaxf(mx, vals[a]);
        }
        float s = 0.f;
        #pragma unroll
        for (int a = 0; a < 32; a++) { vals[a] = expf(vals[a] - mx); s += vals[a]; }
        float inv = 1.f / s;
        int frame = blockIdx.x * 4 + f;
        if (j < 8) {
            size_t base = OFF_A0 + (size_t)(frame * 32) * 8 + j;
            #pragma unroll
            for (int a = 0; a < 32; a++) out[base + (size_t)a * 8] = vals[a] * inv;
        } else if (j < 14) {
            size_t base = OFF_A1 + (size_t)(frame * 32) * 6 + (j - 8);
            #pragma unroll
            for (int a = 0; a < 32; a++) out[base + (size_t)a * 6] = vals[a] * inv;
        } else {
            size_t base = OFF_A2 + (size_t)(frame * 32) * 4 + (j - 14);
            #pragma unroll
            for (int a = 0; a < 32; a++) out[base + (size_t)a * 4] = vals[a] * inv;
        }
    }
    __syncthreads();   // softmax done (sL dead -> W2B region usable)

    // ================= phase 3: gemm2 from smem hid (cp.async W2 db) =========
    const int m2 = (w >> 1) * 32, n2 = (w & 1) * 32;
    for (int c = 0; c < 4; c++) {
        if (c) __syncthreads();                // compute(c-1) done
        if (c < 3)
            stage_w2_async(sbase + (((c + 1) & 1) ? SW2B : SW2A), c + 1, tid);
        CP_COMMIT();
        CP_WAIT1();                            // W2(c) landed
        __syncthreads();

        __half* cW2 = (__half*)(smem + ((c & 1) ? SW2B : SW2A));
        float acc[2][4][4];
        #pragma unroll
        for (int a = 0; a < 2; a++)
            #pragma unroll
            for (int b = 0; b < 4; b++)
                #pragma unroll
                for (int q = 0; q < 4; q++) acc[a][b][q] = 0.f;

        #pragma unroll
        for (int ks = 0; ks < 9; ks++) {
            int k0 = ks * 16;
            uint32_t a[2][4];
            #pragma unroll
            for (int mt = 0; mt < 2; mt++)
                ldsm_x4(a[mt], smaddr(sHid + (m2 + mt * 16 + aRow) * STH + k0 + aKo));
            #pragma unroll
            for (int nt = 0; nt < 4; nt++) {
                uint32_t b[2];
                ldsm_x2(b, smaddr(cW2 + (n2 + nt * 8 + bRow) * STW + k0 + bKo));
                mma_f16(acc[0][nt], a[0], b);
                mma_f16(acc[1][nt], a[1], b);
            }
        }

        #pragma unroll
        for (int mt = 0; mt < 2; mt++) {
            #pragma unroll
            for (int nt = 0; nt < 4; nt++) {
                int col = c * 64 + n2 + nt * 8 + ((lane & 3) << 1);
                int rb = row0 + m2 + mt * 16 + (lane >> 2);
                *(float2*)(out + (size_t)rb * OUT2 + col) =
                    make_float2(acc[mt][nt][0], acc[mt][nt][1]);
                *(float2*)(out + (size_t)(rb + 8) * OUT2 + col) =
                    make_float2(acc[mt][nt][2], acc[mt][nt][3]);
            }
        }
    }
}

// ----------------------------------------------------------------
extern "C" void kernel_launch(void* const* d_in, const int* in_sizes, int n_in,
                              void* d_out, int out_size)
{
    const float* cur  = (const float*)d_in[0];
    const float* nxt  = (const float*)d_in[1];
    const int*   acts = (const int*)  d_in[2];
    const float* W1   = (const float*)d_in[3];
    const float* b1   = (const float*)d_in[4];
    const float* W2   = (const float*)d_in[5];
    const float* b2   = (const float*)d_in[6];
    const float* Wi0  = (const float*)d_in[7];
    const float* Wi1  = (const float*)d_in[9];
    const float* Wi2  = (const float*)d_in[11];
    float* out = (float*)d_out;

    cudaFuncSetAttribute(fused_all, cudaFuncAttributeMaxDynamicSharedMemorySize, SM_TOTAL);

    prep_kernel<<<(N1P * K1P + 255) / 256, 256>>>(W1, b1, W2, b2, Wi0, Wi1, Wi2);
    fused_all<<<N_ROWS / 128, 256, SM_TOTAL>>>(cur, nxt, acts, out);
}